// round 10
// baseline (speedup 1.0000x reference)
#include <cuda_runtime.h>
#include <cuda_fp16.h>
#include <cstdint>

// Problem constants (fixed shapes per reference)
#define NNODES 50000
#define NEDGES 800000
#define DIMF   512
#define NGRAPH 64
#define NCLS   10
#define NB_SCAN ((NNODES + 1023) / 1024)   // 49

// ---------------- device scratch (no allocs allowed) ----------------
__device__ __half g_Xh[(size_t)NNODES * DIMF];   // x in fp16 (layer0 A)
__device__ __half g_Hh[(size_t)NNODES * DIMF];   // layer outputs fp16
__device__ __half g_Yh[(size_t)NNODES * DIMF];   // A @ Wr fp16 (gathered by SpMM)
__device__ __half g_Sh[(size_t)NNODES * DIMF];   // A @ Ws fp16 (self term)
__device__ __half g_Bh0[1024 * 512];             // [Wr0|Ws0]^T as [N=1024, K=512] fp16 K-major
__device__ __half g_Bh1[1024 * 512];             // [Wr1|Ws1]^T
__device__ int   g_cnt[NNODES];
__device__ int   g_cursor[NNODES];
__device__ int   g_rowptr[NNODES + 1];
__device__ int   g_col[NEDGES];
__device__ int   g_bsum[64];
__device__ int   g_boff[64];
__device__ int   g_goff[NGRAPH + 1];
__device__ float g_pooled[NGRAPH * DIMF];

// ---------------- low-level helpers ----------------
__device__ __forceinline__ uint32_t s2u(const void* p) {
    uint32_t a;
    asm("{ .reg .u64 t; cvta.to.shared.u64 t, %1; cvt.u32.u64 %0, t; }" : "=r"(a) : "l"(p));
    return a;
}
__device__ __forceinline__ void cp16(uint32_t d, const void* s) {
    asm volatile("cp.async.cg.shared.global [%0], [%1], 16;\n" :: "r"(d), "l"(s));
}
__device__ __forceinline__ void cp_commit() { asm volatile("cp.async.commit_group;\n" ::: "memory"); }
__device__ __forceinline__ void cp_wait1()  { asm volatile("cp.async.wait_group 1;\n" ::: "memory"); }
__device__ __forceinline__ void cp_wait0()  { asm volatile("cp.async.wait_group 0;\n" ::: "memory"); }

__device__ __forceinline__ void mma16816(float* c, const uint32_t* a, const uint32_t* b) {
    asm volatile(
        "mma.sync.aligned.m16n8k16.row.col.f32.f16.f16.f32 "
        "{%0,%1,%2,%3},{%4,%5,%6,%7},{%8,%9},{%0,%1,%2,%3};"
        : "+f"(c[0]), "+f"(c[1]), "+f"(c[2]), "+f"(c[3])
        : "r"(a[0]), "r"(a[1]), "r"(a[2]), "r"(a[3]), "r"(b[0]), "r"(b[1]));
}
__device__ __forceinline__ void ldsm4(uint32_t* r, uint32_t a) {
    asm volatile("ldmatrix.sync.aligned.m8n8.x4.shared.b16 {%0,%1,%2,%3}, [%4];"
                 : "=r"(r[0]), "=r"(r[1]), "=r"(r[2]), "=r"(r[3]) : "r"(a));
}

// ---------------- setup kernels ----------------
__global__ void zero_buffers() {
    int i = blockIdx.x * 256 + threadIdx.x;
    if (i < NNODES) g_cnt[i] = 0;
    if (i < NGRAPH * DIMF) g_pooled[i] = 0.f;
}

__global__ void hist_edges(const int* __restrict__ ei) {
    int e = blockIdx.x * 256 + threadIdx.x;
    if (e < NEDGES) atomicAdd(&g_cnt[ei[NEDGES + e]], 1);
}

// hierarchical scan stage 1: per-1024-chunk sums
__global__ void scan_blocks() {
    __shared__ int ws[32];
    int t = threadIdx.x, b = blockIdx.x;
    long i = (long)b * 1024 + t;
    int v = (i < NNODES) ? g_cnt[i] : 0;
#pragma unroll
    for (int off = 16; off; off >>= 1) v += __shfl_down_sync(0xffffffffu, v, off);
    if ((t & 31) == 0) ws[t >> 5] = v;
    __syncthreads();
    if (t < 32) {
        int s = ws[t];
#pragma unroll
        for (int off = 16; off; off >>= 1) s += __shfl_down_sync(0xffffffffu, s, off);
        if (t == 0) g_bsum[b] = s;
    }
}

// stage 2: exclusive scan of 49 block sums
__global__ void scan_offsets() {
    __shared__ int sh[64];
    int t = threadIdx.x;
    int v = (t < NB_SCAN) ? g_bsum[t] : 0;
    sh[t] = v;
    __syncthreads();
    for (int off = 1; off < 64; off <<= 1) {
        int a = (t >= off) ? sh[t - off] : 0;
        __syncthreads();
        sh[t] += a;
        __syncthreads();
    }
    if (t < NB_SCAN) g_boff[t] = sh[t] - v;
}

// stage 3: local scan + global offset -> rowptr & cursor
__global__ void scan_write() {
    __shared__ int wsum[32];
    int t = threadIdx.x, b = blockIdx.x, lane = t & 31, w = t >> 5;
    long i = (long)b * 1024 + t;
    int v = (i < NNODES) ? g_cnt[i] : 0;
    int s = v;
#pragma unroll
    for (int off = 1; off < 32; off <<= 1) {
        int n = __shfl_up_sync(0xffffffffu, s, off);
        if (lane >= off) s += n;
    }
    if (lane == 31) wsum[w] = s;
    __syncthreads();
    if (w == 0) {
        int ws = wsum[lane];
#pragma unroll
        for (int off = 1; off < 32; off <<= 1) {
            int n = __shfl_up_sync(0xffffffffu, ws, off);
            if (lane >= off) ws += n;
        }
        wsum[lane] = ws;
    }
    __syncthreads();
    int base = g_boff[b] + ((w > 0) ? wsum[w - 1] : 0);
    if (i < NNODES) {
        g_rowptr[i + 1] = base + s;
        g_cursor[i]     = base + s - v;
    }
    if (b == 0 && t == 0) g_rowptr[0] = 0;
}

__global__ void scatter_edges(const int* __restrict__ ei) {
    int e = blockIdx.x * 256 + threadIdx.x;
    if (e < NEDGES) {
        int dst = ei[NEDGES + e];
        int src = ei[e];
        int pos = atomicAdd(&g_cursor[dst], 1);
        g_col[pos] = src;
    }
}

// batch is sorted -> graph offsets by binary search
__global__ void goff_search(const int* __restrict__ bat) {
    int g = threadIdx.x;
    if (g > NGRAPH) return;
    if (g == NGRAPH) { g_goff[g] = NNODES; return; }
    int lo = 0, hi = NNODES;
    while (lo < hi) {
        int mid = (lo + hi) >> 1;
        if (bat[mid] < g) lo = mid + 1; else hi = mid;
    }
    g_goff[g] = lo;
}

// ---------------- conversion kernels ----------------
__global__ void conv_x(const float* __restrict__ x) {
    long i = (long)blockIdx.x * 256 + threadIdx.x;   // float4 index
    if (i < (long)NNODES * DIMF / 4) {
        float4 v = ((const float4*)x)[i];
        __half2 a = __floats2half2_rn(v.x, v.y);
        __half2 b = __floats2half2_rn(v.z, v.w);
        uint2 u;
        u.x = *(uint32_t*)&a;
        u.y = *(uint32_t*)&b;
        ((uint2*)g_Xh)[i] = u;
    }
}

// Bt[n][k] = (n<512 ? Wr[k][n] : Ws[k][n-512]), fp16. grid (16,32), block (32,8)
__global__ void conv_w(const float* __restrict__ Wr, const float* __restrict__ Ws, int sel) {
    __shared__ float tile[32][33];
    __half* dst = sel ? g_Bh1 : g_Bh0;
    int k0 = blockIdx.x * 32, n0 = blockIdx.y * 32;
    const float* W = (n0 < 512) ? Wr : Ws;
    int ns0 = n0 & 511;
    int tx = threadIdx.x, ty = threadIdx.y;
#pragma unroll
    for (int j = 0; j < 4; j++)
        tile[ty + 8 * j][tx] = W[(long)(k0 + ty + 8 * j) * 512 + ns0 + tx];
    __syncthreads();
#pragma unroll
    for (int j = 0; j < 4; j++)
        dst[(long)(n0 + ty + 8 * j) * 512 + k0 + tx] = __float2half_rn(tile[tx][ty + 8 * j]);
}

// ---------------- fp16 mma.sync GEMM: occupancy-focused ----------------
// CTA tile BM=128 x BN=64, BK=32; 256 threads = 8 warps (4 M x 2 N), warp tile 32x32.
// acc = 32 regs/thread -> 3 CTAs/SM (launch_bounds(256,3)), 3-stage cp.async pipeline.
// Epilogue staged through smem for coalesced STG.
#define SLD   40                       // smem row stride in halfs (32 data + 8 pad)
#define A_STG (128 * SLD * 2)          // 10240 B
#define B_STG (64 * SLD * 2)           // 5120 B
#define STAGE_BYTES (A_STG + B_STG)    // 15360
#define GEMM_SMEM (3 * STAGE_BYTES)    // 46080
#define CLD 72                         // epilogue stage row stride in halfs (64 + 8 pad)

__global__ __launch_bounds__(256, 3)
void gemm_tc16(int aSel, int bSel) {
    extern __shared__ __half dsm[];
    const uint32_t base = s2u(dsm);

    const __half* A  = aSel ? g_Hh : g_Xh;
    const __half* Bt = bSel ? g_Bh1 : g_Bh0;
    const int tid = threadIdx.x, wid = tid >> 5, lane = tid & 31;
    const int wm = (wid & 3) * 32;   // 4 M warp-tiles
    const int wn = (wid >> 2) * 32;  // 2 N warp-tiles
    const int grp = lane >> 2, tg = lane & 3;
    const long bm = (long)blockIdx.x * 128;
    const int  bn = blockIdx.y * 64;

    float acc[2][4][4];
#pragma unroll
    for (int mi = 0; mi < 2; mi++)
#pragma unroll
        for (int ni = 0; ni < 4; ni++)
#pragma unroll
            for (int j = 0; j < 4; j++) acc[mi][ni][j] = 0.f;

    // ldmatrix lane addresses (byte offsets within stage A / stage B)
    const uint32_t aOff = (uint32_t)(((wm + (lane & 15)) * SLD + (lane >> 4) * 8) * 2);
    const uint32_t bOff = (uint32_t)(((wn + (lane & 7) + ((lane >> 4) << 3)) * SLD +
                                      ((lane >> 3) & 1) * 8) * 2);

#define LOAD_STAGE(s, kb)                                                                \
    {                                                                                    \
        uint32_t ab = base + (uint32_t)(s) * STAGE_BYTES;                                \
        uint32_t bb = ab + A_STG;                                                        \
        _Pragma("unroll")                                                                \
        for (int j = 0; j < 2; j++) {   /* A: 512 chunks */                              \
            int c  = tid + 256 * j;                                                      \
            int r  = c >> 2;                                                             \
            int c8 = (c & 3) * 8;                                                        \
            long row = bm + r;                                                           \
            if (row < NNODES)                                                            \
                cp16(ab + (uint32_t)(r * SLD + c8) * 2, A + row * 512 + (kb) + c8);      \
        }                                                                                \
        {   /* B: 256 chunks */                                                          \
            int r  = tid >> 2;                                                           \
            int c8 = (tid & 3) * 8;                                                      \
            cp16(bb + (uint32_t)(r * SLD + c8) * 2, Bt + (long)(bn + r) * 512 + (kb) + c8); \
        }                                                                                \
        cp_commit();                                                                     \
    }

    LOAD_STAGE(0, 0);
    LOAD_STAGE(1, 32);

    int stage = 0;
    for (int kt = 0; kt < 16; kt++) {
        if (kt == 15) cp_wait0(); else cp_wait1();
        __syncthreads();
        if (kt + 2 < 16) {
            int ns = stage + 2; if (ns >= 3) ns -= 3;
            LOAD_STAGE(ns, (kt + 2) * 32);
        }

        const uint32_t sb = base + (uint32_t)stage * STAGE_BYTES;
        const uint32_t aLd = sb + aOff, bLd = sb + A_STG + bOff;
#pragma unroll
        for (int ks = 0; ks < 2; ks++) {
            uint32_t af[2][4], bq[2][4];
#pragma unroll
            for (int mi = 0; mi < 2; mi++)
                ldsm4(af[mi], aLd + (uint32_t)(mi * 16 * SLD * 2 + ks * 32));
#pragma unroll
            for (int nj = 0; nj < 2; nj++)
                ldsm4(bq[nj], bLd + (uint32_t)(nj * 16 * SLD * 2 + ks * 32));
#pragma unroll
            for (int mi = 0; mi < 2; mi++)
#pragma unroll
                for (int ni = 0; ni < 4; ni++)
                    mma16816(acc[mi][ni], af[mi], &bq[ni >> 1][(ni & 1) * 2]);
        }
        if (++stage >= 3) stage -= 3;
    }

    // ---------------- staged epilogue ----------------
    __syncthreads();
#pragma unroll
    for (int mi = 0; mi < 2; mi++) {
#pragma unroll
        for (int ni = 0; ni < 4; ni++) {
            int r = wm + mi * 16 + grp;
            int c = wn + ni * 8 + tg * 2;
            __half2 h0 = __floats2half2_rn(acc[mi][ni][0], acc[mi][ni][1]);
            __half2 h1 = __floats2half2_rn(acc[mi][ni][2], acc[mi][ni][3]);
            *(__half2*)(dsm + r * CLD + c)       = h0;
            *(__half2*)(dsm + (r + 8) * CLD + c) = h1;
        }
    }
    __syncthreads();
    // coalesced writeout: thread -> one 64B chunk (half a 128B row)
    {
        int r  = tid >> 1;
        int hb = (tid & 1) * 32;   // half offset within the 64-col tile
        long grow = bm + r;
        if (grow < NNODES) {
            int gcol = bn + hb;    // bn multiple of 64: whole tile on one side of split
            __half* bp = (gcol < 512) ? (g_Yh + grow * 512 + gcol)
                                      : (g_Sh + grow * 512 + (gcol - 512));
            const uint4* src = (const uint4*)(dsm + r * CLD + hb);
#pragma unroll
            for (int q = 0; q < 4; q++) ((uint4*)bp)[q] = src[q];
        }
    }
#undef LOAD_STAGE
}

// ---------------- SpMM: Hh[i] = relu( Sh[i] + br + sum_{j in N(i)} Yh[j] ) ----------------
__global__ void spmm_f16(const float* __restrict__ br) {
    int i = blockIdx.x;
    int t = threadIdx.x;   // 128 threads x 4 features
    int s = g_rowptr[i], e = g_rowptr[i + 1];

    uint2 su = *(const uint2*)(g_Sh + (long)i * 512 + t * 4);
    float2 s0 = __half22float2(*(__half2*)&su.x), s1 = __half22float2(*(__half2*)&su.y);
    float4 b = *(const float4*)(br + t * 4);
    float4 acc = make_float4(s0.x + b.x, s0.y + b.y, s1.x + b.z, s1.y + b.w);

    int p = s;
    for (; p + 1 < e; p += 2) {
        int j0 = __ldg(&g_col[p]);
        int j1 = __ldg(&g_col[p + 1]);
        uint2 u0 = *(const uint2*)(g_Yh + (long)j0 * 512 + t * 4);
        uint2 u1 = *(const uint2*)(g_Yh + (long)j1 * 512 + t * 4);
        float2 a0 = __half22float2(*(__half2*)&u0.x), a1 = __half22float2(*(__half2*)&u0.y);
        float2 c0 = __half22float2(*(__half2*)&u1.x), c1 = __half22float2(*(__half2*)&u1.y);
        acc.x += a0.x + c0.x; acc.y += a0.y + c0.y;
        acc.z += a1.x + c1.x; acc.w += a1.y + c1.y;
    }
    if (p < e) {
        int j = __ldg(&g_col[p]);
        uint2 u = *(const uint2*)(g_Yh + (long)j * 512 + t * 4);
        float2 f0 = __half22float2(*(__half2*)&u.x), f1 = __half22float2(*(__half2*)&u.y);
        acc.x += f0.x; acc.y += f0.y; acc.z += f1.x; acc.w += f1.y;
    }
    acc.x = fmaxf(acc.x, 0.f);
    acc.y = fmaxf(acc.y, 0.f);
    acc.z = fmaxf(acc.z, 0.f);
    acc.w = fmaxf(acc.w, 0.f);

    __half2 o0 = __floats2half2_rn(acc.x, acc.y);
    __half2 o1 = __floats2half2_rn(acc.z, acc.w);
    uint2 st;
    st.x = *(uint32_t*)&o0;
    st.y = *(uint32_t*)&o1;
    *(uint2*)(g_Hh + (long)i * 512 + t * 4) = st;
}

// ---------------- pooling + classifier ----------------
__global__ void pool_partial() {
    int g = blockIdx.x, ch = blockIdx.y;
    int t = threadIdx.x;   // 128
    int s = g_goff[g], e = g_goff[g + 1];
    float4 acc = make_float4(0.f, 0.f, 0.f, 0.f);
    for (int n = s + ch; n < e; n += gridDim.y) {
        uint2 u = *(const uint2*)(g_Hh + (long)n * 512 + t * 4);
        float2 f0 = __half22float2(*(__half2*)&u.x), f1 = __half22float2(*(__half2*)&u.y);
        acc.x += f0.x; acc.y += f0.y; acc.z += f1.x; acc.w += f1.y;
    }
    float* dst = &g_pooled[g * 512 + t * 4];
    atomicAdd(dst + 0, acc.x);
    atomicAdd(dst + 1, acc.y);
    atomicAdd(dst + 2, acc.z);
    atomicAdd(dst + 3, acc.w);
}

// fused: mean + relu + linear
__global__ void final_linear(const float* __restrict__ Wl, const float* __restrict__ bl,
                             float* __restrict__ out) {
    __shared__ float sh[512];
    int g = blockIdx.x, t = threadIdx.x;   // 320 threads
    int cnt = g_goff[g + 1] - g_goff[g];
    float inv = 1.f / (float)(cnt > 0 ? cnt : 1);
    for (int f = t; f < 512; f += blockDim.x) {
        float v = g_pooled[g * 512 + f] * inv;
        sh[f] = v > 0.f ? v : 0.f;
    }
    __syncthreads();
    int w = t >> 5, lane = t & 31;
    if (w < NCLS) {
        float s = 0.f;
        for (int f = lane; f < 512; f += 32) s += sh[f] * Wl[f * NCLS + w];
#pragma unroll
        for (int o = 16; o; o >>= 1) s += __shfl_down_sync(0xffffffffu, s, o);
        if (lane == 0) out[g * NCLS + w] = s + bl[w];
    }
}

// ---------------- launch ----------------
extern "C" void kernel_launch(void* const* d_in, const int* in_sizes, int n_in,
                              void* d_out, int out_size) {
    const float* x   = (const float*)d_in[0];
    const int*   ei  = (const int*)d_in[1];
    const int*   bat = (const int*)d_in[2];
    const float* Wr0 = (const float*)d_in[3];
    const float* br0 = (const float*)d_in[4];
    const float* Ws0 = (const float*)d_in[5];
    const float* Wr1 = (const float*)d_in[6];
    const float* br1 = (const float*)d_in[7];
    const float* Ws1 = (const float*)d_in[8];
    const float* Wl  = (const float*)d_in[9];
    const float* bl  = (const float*)d_in[10];
    float* out = (float*)d_out;

    static cudaStream_t s1 = nullptr;
    static cudaEvent_t  e0 = nullptr, e1 = nullptr;
    if (!s1) {
        cudaStreamCreateWithFlags(&s1, cudaStreamNonBlocking);
        cudaEventCreateWithFlags(&e0, cudaEventDisableTiming);
        cudaEventCreateWithFlags(&e1, cudaEventDisableTiming);
        cudaFuncSetAttribute(gemm_tc16, cudaFuncAttributeMaxDynamicSharedMemorySize, GEMM_SMEM);
    }

    const int NBLK = (NNODES + 255) / 256;
    const int EBLK = (NEDGES + 255) / 256;
    dim3 ggrid((NNODES + 127) / 128, 16);   // 391 M-tiles x 16 N-tiles(64) over N=1024

    // fork side stream at entry (CSR chain runs concurrently with convs + gemm0)
    cudaEventRecord(e0, 0);
    cudaStreamWaitEvent(s1, e0, 0);

    // main stream: conv_x(1), conv_w0(2), conv_w1(3), gemm0(4 -> profiled)
    conv_x<<<(NNODES * DIMF / 4 + 255) / 256, 256>>>(x);
    conv_w<<<dim3(16, 32), dim3(32, 8)>>>(Wr0, Ws0, 0);
    conv_w<<<dim3(16, 32), dim3(32, 8)>>>(Wr1, Ws1, 1);
    gemm_tc16<<<ggrid, 256, GEMM_SMEM>>>(0, 0);

    // side stream: CSR + batch structure
    zero_buffers<<<NBLK, 256, 0, s1>>>();
    hist_edges<<<EBLK, 256, 0, s1>>>(ei);
    scan_blocks<<<NB_SCAN, 1024, 0, s1>>>();
    scan_offsets<<<1, 64, 0, s1>>>();
    scan_write<<<NB_SCAN, 1024, 0, s1>>>();
    scatter_edges<<<EBLK, 256, 0, s1>>>(ei);
    goff_search<<<1, 128, 0, s1>>>(bat);
    cudaEventRecord(e1, s1);

    // join: spmm needs CSR
    cudaStreamWaitEvent(0, e1, 0);
    spmm_f16<<<NNODES, 128>>>(br0);

    // layer 1
    gemm_tc16<<<ggrid, 256, GEMM_SMEM>>>(1, 1);
    spmm_f16<<<NNODES, 128>>>(br1);

    // pool + classify
    pool_partial<<<dim3(NGRAPH, 16), 128>>>();
    final_linear<<<NGRAPH, 320>>>(Wl, bl, out);
}

// round 11
// speedup vs baseline: 1.0687x; 1.0687x over previous
#include <cuda_runtime.h>
#include <cuda_fp16.h>
#include <cstdint>

// Problem constants (fixed shapes per reference)
#define NNODES 50000
#define NEDGES 800000
#define DIMF   512
#define NGRAPH 64
#define NCLS   10
#define NB_SCAN ((NNODES + 1023) / 1024)   // 49

// ---------------- device scratch (no allocs allowed) ----------------
__device__ __half g_Xh[(size_t)NNODES * DIMF];   // x in fp16 (layer0 A)
__device__ __half g_Hh[(size_t)NNODES * DIMF];   // layer outputs fp16
__device__ __half g_Yh[(size_t)NNODES * DIMF];   // A @ Wr fp16 (gathered by SpMM)
__device__ __half g_Sh[(size_t)NNODES * DIMF];   // A @ Ws fp16 (self term)
__device__ __half g_Bh0[1024 * 512];             // [Wr0|Ws0]^T as [N=1024, K=512] fp16 K-major
__device__ __half g_Bh1[1024 * 512];             // [Wr1|Ws1]^T
__device__ int   g_cnt[NNODES];
__device__ int   g_cursor[NNODES];
__device__ int   g_rowptr[NNODES + 1];
__device__ int   g_col[NEDGES];
__device__ int   g_bsum[64];
__device__ int   g_boff[64];
__device__ int   g_goff[NGRAPH + 1];
__device__ float g_pooled[NGRAPH * DIMF];

// ---------------- low-level helpers ----------------
__device__ __forceinline__ uint32_t s2u(const void* p) {
    uint32_t a;
    asm("{ .reg .u64 t; cvta.to.shared.u64 t, %1; cvt.u32.u64 %0, t; }" : "=r"(a) : "l"(p));
    return a;
}
__device__ __forceinline__ void cp16(uint32_t d, const void* s) {
    asm volatile("cp.async.cg.shared.global [%0], [%1], 16;\n" :: "r"(d), "l"(s));
}
__device__ __forceinline__ void cp_commit() { asm volatile("cp.async.commit_group;\n" ::: "memory"); }
__device__ __forceinline__ void cp_wait1()  { asm volatile("cp.async.wait_group 1;\n" ::: "memory"); }
__device__ __forceinline__ void cp_wait0()  { asm volatile("cp.async.wait_group 0;\n" ::: "memory"); }

// fp16-accumulate HMMA: 2x rate vs f32-accum, half the accumulator registers
__device__ __forceinline__ void mma16816h(uint32_t* c, const uint32_t* a, const uint32_t* b) {
    asm volatile(
        "mma.sync.aligned.m16n8k16.row.col.f16.f16.f16.f16 "
        "{%0,%1},{%2,%3,%4,%5},{%6,%7},{%0,%1};"
        : "+r"(c[0]), "+r"(c[1])
        : "r"(a[0]), "r"(a[1]), "r"(a[2]), "r"(a[3]), "r"(b[0]), "r"(b[1]));
}
__device__ __forceinline__ void ldsm4(uint32_t* r, uint32_t a) {
    asm volatile("ldmatrix.sync.aligned.m8n8.x4.shared.b16 {%0,%1,%2,%3}, [%4];"
                 : "=r"(r[0]), "=r"(r[1]), "=r"(r[2]), "=r"(r[3]) : "r"(a));
}

// ---------------- setup kernels ----------------
__global__ void zero_buffers() {
    int i = blockIdx.x * 256 + threadIdx.x;
    if (i < NNODES) g_cnt[i] = 0;
    if (i < NGRAPH * DIMF) g_pooled[i] = 0.f;
}

__global__ void hist_edges(const int* __restrict__ ei) {
    int e = blockIdx.x * 256 + threadIdx.x;
    if (e < NEDGES) atomicAdd(&g_cnt[ei[NEDGES + e]], 1);
}

// hierarchical scan stage 1: per-1024-chunk sums
__global__ void scan_blocks() {
    __shared__ int ws[32];
    int t = threadIdx.x, b = blockIdx.x;
    long i = (long)b * 1024 + t;
    int v = (i < NNODES) ? g_cnt[i] : 0;
#pragma unroll
    for (int off = 16; off; off >>= 1) v += __shfl_down_sync(0xffffffffu, v, off);
    if ((t & 31) == 0) ws[t >> 5] = v;
    __syncthreads();
    if (t < 32) {
        int s = ws[t];
#pragma unroll
        for (int off = 16; off; off >>= 1) s += __shfl_down_sync(0xffffffffu, s, off);
        if (t == 0) g_bsum[b] = s;
    }
}

// stage 2: exclusive scan of 49 block sums
__global__ void scan_offsets() {
    __shared__ int sh[64];
    int t = threadIdx.x;
    int v = (t < NB_SCAN) ? g_bsum[t] : 0;
    sh[t] = v;
    __syncthreads();
    for (int off = 1; off < 64; off <<= 1) {
        int a = (t >= off) ? sh[t - off] : 0;
        __syncthreads();
        sh[t] += a;
        __syncthreads();
    }
    if (t < NB_SCAN) g_boff[t] = sh[t] - v;
}

// stage 3: local scan + global offset -> rowptr & cursor
__global__ void scan_write() {
    __shared__ int wsum[32];
    int t = threadIdx.x, b = blockIdx.x, lane = t & 31, w = t >> 5;
    long i = (long)b * 1024 + t;
    int v = (i < NNODES) ? g_cnt[i] : 0;
    int s = v;
#pragma unroll
    for (int off = 1; off < 32; off <<= 1) {
        int n = __shfl_up_sync(0xffffffffu, s, off);
        if (lane >= off) s += n;
    }
    if (lane == 31) wsum[w] = s;
    __syncthreads();
    if (w == 0) {
        int ws = wsum[lane];
#pragma unroll
        for (int off = 1; off < 32; off <<= 1) {
            int n = __shfl_up_sync(0xffffffffu, ws, off);
            if (lane >= off) ws += n;
        }
        wsum[lane] = ws;
    }
    __syncthreads();
    int base = g_boff[b] + ((w > 0) ? wsum[w - 1] : 0);
    if (i < NNODES) {
        g_rowptr[i + 1] = base + s;
        g_cursor[i]     = base + s - v;
    }
    if (b == 0 && t == 0) g_rowptr[0] = 0;
}

__global__ void scatter_edges(const int* __restrict__ ei) {
    int e = blockIdx.x * 256 + threadIdx.x;
    if (e < NEDGES) {
        int dst = ei[NEDGES + e];
        int src = ei[e];
        int pos = atomicAdd(&g_cursor[dst], 1);
        g_col[pos] = src;
    }
}

// batch is sorted -> graph offsets by binary search
__global__ void goff_search(const int* __restrict__ bat) {
    int g = threadIdx.x;
    if (g > NGRAPH) return;
    if (g == NGRAPH) { g_goff[g] = NNODES; return; }
    int lo = 0, hi = NNODES;
    while (lo < hi) {
        int mid = (lo + hi) >> 1;
        if (bat[mid] < g) lo = mid + 1; else hi = mid;
    }
    g_goff[g] = lo;
}

// ---------------- conversion kernels ----------------
__global__ void conv_x(const float* __restrict__ x) {
    long i = (long)blockIdx.x * 256 + threadIdx.x;   // float4 index
    if (i < (long)NNODES * DIMF / 4) {
        float4 v = ((const float4*)x)[i];
        __half2 a = __floats2half2_rn(v.x, v.y);
        __half2 b = __floats2half2_rn(v.z, v.w);
        uint2 u;
        u.x = *(uint32_t*)&a;
        u.y = *(uint32_t*)&b;
        ((uint2*)g_Xh)[i] = u;
    }
}

// Bt[n][k] = (n<512 ? Wr[k][n] : Ws[k][n-512]), fp16. grid (16,32), block (32,8)
__global__ void conv_w(const float* __restrict__ Wr, const float* __restrict__ Ws, int sel) {
    __shared__ float tile[32][33];
    __half* dst = sel ? g_Bh1 : g_Bh0;
    int k0 = blockIdx.x * 32, n0 = blockIdx.y * 32;
    const float* W = (n0 < 512) ? Wr : Ws;
    int ns0 = n0 & 511;
    int tx = threadIdx.x, ty = threadIdx.y;
#pragma unroll
    for (int j = 0; j < 4; j++)
        tile[ty + 8 * j][tx] = W[(long)(k0 + ty + 8 * j) * 512 + ns0 + tx];
    __syncthreads();
#pragma unroll
    for (int j = 0; j < 4; j++)
        dst[(long)(n0 + ty + 8 * j) * 512 + k0 + tx] = __float2half_rn(tile[tx][ty + 8 * j]);
}

// ---------------- fp16-accum mma.sync GEMM ----------------
// CTA tile BM=128 x BN=128, BK=32; 256 threads = 8 warps (2 M x 4 N), warp tile 64x32.
// fp16 accumulators (16 regs/warp-tile-row-pair) -> ~70 regs -> 3 CTAs/SM.
// 3-stage cp.async pipeline; staged smem epilogue, direct fp16 stores (no convert).
#define SLD   40                       // smem row stride in halfs (32 data + 8 pad)
#define STG_B (128 * SLD * 2)          // 10240 B per A (or B) stage
#define STAGE_BYTES (2 * STG_B)        // 20480
#define GEMM_SMEM (3 * STAGE_BYTES)    // 61440  (3 CTAs/SM = 184 KB <= 228 KB)
#define CLD 136                        // epilogue stage row stride in halfs

__global__ __launch_bounds__(256, 3)
void gemm_tc16(int aSel, int bSel) {
    extern __shared__ __half dsm[];
    const uint32_t base = s2u(dsm);

    const __half* A  = aSel ? g_Hh : g_Xh;
    const __half* Bt = bSel ? g_Bh1 : g_Bh0;
    const int tid = threadIdx.x, wid = tid >> 5, lane = tid & 31;
    const int wm = (wid >> 2) * 64, wn = (wid & 3) * 32;
    const int grp = lane >> 2, tg = lane & 3;
    const long bm = (long)blockIdx.x * 128;
    const int  bn = blockIdx.y * 128;

    // fp16 accumulators: [mi][ni][0] = row r (half2 cols c,c+1), [1] = row r+8
    uint32_t acc[4][4][2];
#pragma unroll
    for (int mi = 0; mi < 4; mi++)
#pragma unroll
        for (int ni = 0; ni < 4; ni++) { acc[mi][ni][0] = 0u; acc[mi][ni][1] = 0u; }

    const uint32_t aOff = (uint32_t)(((wm + (lane & 15)) * SLD + (lane >> 4) * 8) * 2);
    const uint32_t bOff = (uint32_t)(((wn + (lane & 7) + ((lane >> 4) << 3)) * SLD +
                                      ((lane >> 3) & 1) * 8) * 2);

#define LOAD_STAGE(s, kb)                                                                \
    {                                                                                    \
        uint32_t ab = base + (uint32_t)(s) * STAGE_BYTES;                                \
        uint32_t bb = ab + STG_B;                                                        \
        _Pragma("unroll")                                                                \
        for (int j = 0; j < 2; j++) {                                                    \
            int c  = tid + 256 * j;                                                      \
            int r  = c >> 2;                                                             \
            int c8 = (c & 3) * 8;                                                        \
            long row = bm + r;                                                           \
            if (row < NNODES)                                                            \
                cp16(ab + (uint32_t)(r * SLD + c8) * 2, A + row * 512 + (kb) + c8);      \
            cp16(bb + (uint32_t)(r * SLD + c8) * 2, Bt + (long)(bn + r) * 512 + (kb) + c8); \
        }                                                                                \
        cp_commit();                                                                     \
    }

    LOAD_STAGE(0, 0);
    LOAD_STAGE(1, 32);

    int stage = 0;
    for (int kt = 0; kt < 16; kt++) {
        if (kt == 15) cp_wait0(); else cp_wait1();
        __syncthreads();
        if (kt + 2 < 16) {
            int ns = stage + 2; if (ns >= 3) ns -= 3;
            LOAD_STAGE(ns, (kt + 2) * 32);
        }

        const uint32_t sb = base + (uint32_t)stage * STAGE_BYTES;
        const uint32_t aLd = sb + aOff, bLd = sb + STG_B + bOff;
#pragma unroll
        for (int ks = 0; ks < 2; ks++) {
            uint32_t af[4][4], bq[2][4];
#pragma unroll
            for (int mi = 0; mi < 4; mi++)
                ldsm4(af[mi], aLd + (uint32_t)(mi * 16 * SLD * 2 + ks * 32));
#pragma unroll
            for (int nj = 0; nj < 2; nj++)
                ldsm4(bq[nj], bLd + (uint32_t)(nj * 16 * SLD * 2 + ks * 32));
#pragma unroll
            for (int mi = 0; mi < 4; mi++)
#pragma unroll
                for (int ni = 0; ni < 4; ni++)
                    mma16816h(acc[mi][ni], af[mi], &bq[ni >> 1][(ni & 1) * 2]);
        }
        if (++stage >= 3) stage -= 3;
    }

    // ---------------- staged epilogue (acc already fp16) ----------------
    __syncthreads();
#pragma unroll
    for (int mi = 0; mi < 4; mi++) {
#pragma unroll
        for (int ni = 0; ni < 4; ni++) {
            int r = wm + mi * 16 + grp;
            int c = wn + ni * 8 + tg * 2;
            *(uint32_t*)(dsm + r * CLD + c)       = acc[mi][ni][0];
            *(uint32_t*)(dsm + (r + 8) * CLD + c) = acc[mi][ni][1];
        }
    }
    __syncthreads();
    // coalesced writeout: thread -> one 128B row-half
    {
        int r  = tid >> 1;
        int hb = (tid & 1) * 64;
        long grow = bm + r;
        if (grow < NNODES) {
            int gcol = bn + hb;   // 64-col chunk entirely on one side of the 512 split
            __half* bp = (gcol < 512) ? (g_Yh + grow * 512 + gcol)
                                      : (g_Sh + grow * 512 + (gcol - 512));
            const uint4* src = (const uint4*)(dsm + r * CLD + hb);
#pragma unroll
            for (int q = 0; q < 8; q++) ((uint4*)bp)[q] = src[q];
        }
    }
#undef LOAD_STAGE
}

// ---------------- SpMM: Hh[i] = relu( Sh[i] + br + sum_{j in N(i)} Yh[j] ) ----------------
__global__ void spmm_f16(const float* __restrict__ br) {
    int i = blockIdx.x;
    int t = threadIdx.x;   // 128 threads x 4 features
    int s = g_rowptr[i], e = g_rowptr[i + 1];

    uint2 su = *(const uint2*)(g_Sh + (long)i * 512 + t * 4);
    float2 s0 = __half22float2(*(__half2*)&su.x), s1 = __half22float2(*(__half2*)&su.y);
    float4 b = *(const float4*)(br + t * 4);
    float4 acc = make_float4(s0.x + b.x, s0.y + b.y, s1.x + b.z, s1.y + b.w);

    int p = s;
    for (; p + 1 < e; p += 2) {
        int j0 = __ldg(&g_col[p]);
        int j1 = __ldg(&g_col[p + 1]);
        uint2 u0 = *(const uint2*)(g_Yh + (long)j0 * 512 + t * 4);
        uint2 u1 = *(const uint2*)(g_Yh + (long)j1 * 512 + t * 4);
        float2 a0 = __half22float2(*(__half2*)&u0.x), a1 = __half22float2(*(__half2*)&u0.y);
        float2 c0 = __half22float2(*(__half2*)&u1.x), c1 = __half22float2(*(__half2*)&u1.y);
        acc.x += a0.x + c0.x; acc.y += a0.y + c0.y;
        acc.z += a1.x + c1.x; acc.w += a1.y + c1.y;
    }
    if (p < e) {
        int j = __ldg(&g_col[p]);
        uint2 u = *(const uint2*)(g_Yh + (long)j * 512 + t * 4);
        float2 f0 = __half22float2(*(__half2*)&u.x), f1 = __half22float2(*(__half2*)&u.y);
        acc.x += f0.x; acc.y += f0.y; acc.z += f1.x; acc.w += f1.y;
    }
    acc.x = fmaxf(acc.x, 0.f);
    acc.y = fmaxf(acc.y, 0.f);
    acc.z = fmaxf(acc.z, 0.f);
    acc.w = fmaxf(acc.w, 0.f);

    __half2 o0 = __floats2half2_rn(acc.x, acc.y);
    __half2 o1 = __floats2half2_rn(acc.z, acc.w);
    uint2 st;
    st.x = *(uint32_t*)&o0;
    st.y = *(uint32_t*)&o1;
    *(uint2*)(g_Hh + (long)i * 512 + t * 4) = st;
}

// ---------------- pooling + classifier ----------------
__global__ void pool_partial() {
    int g = blockIdx.x, ch = blockIdx.y;
    int t = threadIdx.x;   // 128
    int s = g_goff[g], e = g_goff[g + 1];
    float4 acc = make_float4(0.f, 0.f, 0.f, 0.f);
    for (int n = s + ch; n < e; n += gridDim.y) {
        uint2 u = *(const uint2*)(g_Hh + (long)n * 512 + t * 4);
        float2 f0 = __half22float2(*(__half2*)&u.x), f1 = __half22float2(*(__half2*)&u.y);
        acc.x += f0.x; acc.y += f0.y; acc.z += f1.x; acc.w += f1.y;
    }
    float* dst = &g_pooled[g * 512 + t * 4];
    atomicAdd(dst + 0, acc.x);
    atomicAdd(dst + 1, acc.y);
    atomicAdd(dst + 2, acc.z);
    atomicAdd(dst + 3, acc.w);
}

// fused: mean + relu + linear
__global__ void final_linear(const float* __restrict__ Wl, const float* __restrict__ bl,
                             float* __restrict__ out) {
    __shared__ float sh[512];
    int g = blockIdx.x, t = threadIdx.x;   // 320 threads
    int cnt = g_goff[g + 1] - g_goff[g];
    float inv = 1.f / (float)(cnt > 0 ? cnt : 1);
    for (int f = t; f < 512; f += blockDim.x) {
        float v = g_pooled[g * 512 + f] * inv;
        sh[f] = v > 0.f ? v : 0.f;
    }
    __syncthreads();
    int w = t >> 5, lane = t & 31;
    if (w < NCLS) {
        float s = 0.f;
        for (int f = lane; f < 512; f += 32) s += sh[f] * Wl[f * NCLS + w];
#pragma unroll
        for (int o = 16; o; o >>= 1) s += __shfl_down_sync(0xffffffffu, s, o);
        if (lane == 0) out[g * NCLS + w] = s + bl[w];
    }
}

// ---------------- launch ----------------
extern "C" void kernel_launch(void* const* d_in, const int* in_sizes, int n_in,
                              void* d_out, int out_size) {
    const float* x   = (const float*)d_in[0];
    const int*   ei  = (const int*)d_in[1];
    const int*   bat = (const int*)d_in[2];
    const float* Wr0 = (const float*)d_in[3];
    const float* br0 = (const float*)d_in[4];
    const float* Ws0 = (const float*)d_in[5];
    const float* Wr1 = (const float*)d_in[6];
    const float* br1 = (const float*)d_in[7];
    const float* Ws1 = (const float*)d_in[8];
    const float* Wl  = (const float*)d_in[9];
    const float* bl  = (const float*)d_in[10];
    float* out = (float*)d_out;

    static cudaStream_t s1 = nullptr;
    static cudaEvent_t  e0 = nullptr, e1 = nullptr;
    if (!s1) {
        cudaStreamCreateWithFlags(&s1, cudaStreamNonBlocking);
        cudaEventCreateWithFlags(&e0, cudaEventDisableTiming);
        cudaEventCreateWithFlags(&e1, cudaEventDisableTiming);
        cudaFuncSetAttribute(gemm_tc16, cudaFuncAttributeMaxDynamicSharedMemorySize, GEMM_SMEM);
    }

    const int NBLK = (NNODES + 255) / 256;
    const int EBLK = (NEDGES + 255) / 256;
    dim3 ggrid((NNODES + 127) / 128, 8);   // 391 M-tiles x 8 N-tiles(128) over N=1024

    // fork side stream at entry (CSR chain runs concurrently with convs + gemm0)
    cudaEventRecord(e0, 0);
    cudaStreamWaitEvent(s1, e0, 0);

    // main stream: conv_x(1), conv_w0(2), conv_w1(3), gemm0(4 -> profiled)
    conv_x<<<(NNODES * DIMF / 4 + 255) / 256, 256>>>(x);
    conv_w<<<dim3(16, 32), dim3(32, 8)>>>(Wr0, Ws0, 0);
    conv_w<<<dim3(16, 32), dim3(32, 8)>>>(Wr1, Ws1, 1);
    gemm_tc16<<<ggrid, 256, GEMM_SMEM>>>(0, 0);

    // side stream: CSR + batch structure
    zero_buffers<<<NBLK, 256, 0, s1>>>();
    hist_edges<<<EBLK, 256, 0, s1>>>(ei);
    scan_blocks<<<NB_SCAN, 1024, 0, s1>>>();
    scan_offsets<<<1, 64, 0, s1>>>();
    scan_write<<<NB_SCAN, 1024, 0, s1>>>();
    scatter_edges<<<EBLK, 256, 0, s1>>>(ei);
    goff_search<<<1, 128, 0, s1>>>(bat);
    cudaEventRecord(e1, s1);

    // join: spmm needs CSR
    cudaStreamWaitEvent(0, e1, 0);
    spmm_f16<<<NNODES, 128>>>(br0);

    // layer 1
    gemm_tc16<<<ggrid, 256, GEMM_SMEM>>>(1, 1);
    spmm_f16<<<NNODES, 128>>>(br1);

    // pool + classify
    pool_partial<<<dim3(NGRAPH, 16), 128>>>();
    final_linear<<<NGRAPH, 320>>>(Wl, bl, out);
}